// round 8
// baseline (speedup 1.0000x reference)
#include <cuda_runtime.h>
#include <cuda_bf16.h>
#include <cstdint>
#include <math.h>

// Problem dims
#define B_  64
#define L_  196
#define D_  2048
#define I_  512
#define M_  (B_ * L_)   // 12544

// Scratch (allocation-free: __device__ globals)
__device__ float g_hs [B_ * I_];          // hs_shaped + b_h + b_f   [B, I]
__device__ float g_t  [(size_t)M_ * I_];  // fv@W_f + bias (tf32)    [B*L, I]
__device__ float g_Wft[(size_t)I_ * D_];  // W_f^T (tf32)            [I, D]
__device__ float g_Wat[(size_t)D_ * I_];  // W_a^T (tf32)            [D, I]

// ---------------------------------------------------------------------------
// helpers
// ---------------------------------------------------------------------------
__device__ __forceinline__ uint32_t smem_u32(const void* p) {
    uint32_t a;
    asm("{ .reg .u64 t; cvta.to.shared.u64 t, %1; cvt.u32.u64 %0, t; }"
        : "=r"(a) : "l"(p));
    return a;
}

// round-to-nearest to tf32 (keep top 19 bits)
__device__ __forceinline__ float to_tf32(float v) {
    uint32_t u = __float_as_uint(v);
    u = (u + 0x1000u) & 0xFFFFE000u;
    return __uint_as_float(u);
}

#define MMA_TF32(c, a, b) \
    asm volatile("mma.sync.aligned.m16n8k8.row.col.f32.tf32.tf32.f32 " \
        "{%0,%1,%2,%3}, {%4,%5,%6,%7}, {%8,%9}, {%0,%1,%2,%3};" \
        : "+f"((c)[0]), "+f"((c)[1]), "+f"((c)[2]), "+f"((c)[3]) \
        : "r"((a)[0]), "r"((a)[1]), "r"((a)[2]), "r"((a)[3]), \
          "r"((b)[0]), "r"((b)[1]))

#define CP_ASYNC16(saddr, gptr) \
    asm volatile("cp.async.cg.shared.global [%0], [%1], 16;" \
                 :: "r"(saddr), "l"(gptr) : "memory")

__device__ __forceinline__ uint32_t lds32(const char* base, uint32_t off) {
    return *(const uint32_t*)(base + off);
}

// ---------------------------------------------------------------------------
// Kernel A: g_hs[b,i] = b_f[i] + b_h[i] + sum_k hidden[b,k] * W_h[k,i]
// ---------------------------------------------------------------------------
__global__ __launch_bounds__(128)
void hs_kernel(const float* __restrict__ hidden,
               const float* __restrict__ W_h,
               const float* __restrict__ b_h,
               const float* __restrict__ b_f,
               float* __restrict__ out)
{
    __shared__ float h[I_];
    const int b = blockIdx.x;
    for (int k = threadIdx.x; k < I_; k += 128)
        h[k] = hidden[b * I_ + k];
    __syncthreads();

    const int i = blockIdx.y * 128 + threadIdx.x;
    float acc = b_h[i] + b_f[i];
    #pragma unroll 8
    for (int k = 0; k < I_; k++)
        acc = fmaf(h[k], W_h[(size_t)k * I_ + i], acc);
    out[b * I_ + i] = acc;
}

// ---------------------------------------------------------------------------
// Transpose + tf32 round: in[R][C] -> out[C][R]
// ---------------------------------------------------------------------------
__global__ __launch_bounds__(256)
void transpose_k(const float* __restrict__ in, float* __restrict__ out,
                 int R, int Cc)
{
    __shared__ float t[32][33];
    const int bx = blockIdx.x * 32;
    const int by = blockIdx.y * 32;
    const int x = threadIdx.x, y = threadIdx.y;
    #pragma unroll
    for (int i = 0; i < 32; i += 8)
        t[y + i][x] = in[(size_t)(by + y + i) * Cc + bx + x];
    __syncthreads();
    #pragma unroll
    for (int i = 0; i < 32; i += 8)
        out[(size_t)(bx + y + i) * R + by + x] = to_tf32(t[x][y + i]);
}

// ---------------------------------------------------------------------------
// tf32 mma.sync GEMM: C[M,N] = A[M,K] @ Bt[N,K]^T (+bias[N]) (+rowBias)
// CTA 128x128x32, 128 threads (4 warps, warp tile 64x64), 3 stages (96KB),
// 2 CTAs/SM. 1.0 LDS per MMA; 32 independent MMAs per k-step.
// ---------------------------------------------------------------------------
#define NSTAGE 3
#define STAGE_BYTES 32768           // A 16KB + B 16KB
#define SMEM_BYTES (NSTAGE * STAGE_BYTES)

__global__ __launch_bounds__(128, 2)
void gemm_tc(int M, int N, int K,
             const float* __restrict__ A,
             const float* __restrict__ Bt,
             float* __restrict__ C,
             const float* __restrict__ bias,
             const float* __restrict__ rowBias,
             int rowsPerBatch, int cvtOut)
{
    extern __shared__ __align__(128) char smem[];
    const uint32_t sbase = smem_u32(smem);
    const int tid = threadIdx.x;
    const int wid = tid >> 5;
    const int lid = tid & 31;
    const int g   = lid >> 2;      // 0..7
    const int t4  = lid & 3;       // 0..3

    const int m0 = (wid >> 1) * 64;
    const int n0 = (wid & 1) * 64;

    const int crow = blockIdx.y, ccol = blockIdx.x;
    const float* Ab = A  + (size_t)crow * 128 * K;
    const float* Bb = Bt + (size_t)ccol * 128 * K;

    // Precomputed fragment base offsets (ks folded in via XOR of bits 5..6).
    uint32_t aOff[4], bOff[8];
    {
        const uint32_t c0 = t4 * 4;
        #pragma unroll
        for (int mt = 0; mt < 4; mt++) {
            const int row = m0 + mt * 16 + g;
            aOff[mt] = row * 128 + (c0 ^ ((row & 7) << 4));
        }
        #pragma unroll
        for (int nt = 0; nt < 8; nt++) {
            const int row = n0 + nt * 8 + g;
            bOff[nt] = row * 128 + (c0 ^ ((row & 7) << 4));
        }
    }

    // Strided gmem->smem copy base (row stride 16 keeps swizzle phase fixed)
    const int r0 = tid >> 3;            // 0..15
    const int c4 = tid & 7;
    const uint32_t swz0 = r0 * 128 + ((c4 << 4) ^ ((r0 & 7) << 4));
    const float* ag0 = Ab + (size_t)r0 * K + c4 * 4;
    const float* bg0 = Bb + (size_t)r0 * K + c4 * 4;

    float cfr[4][8][4];
    #pragma unroll
    for (int mt = 0; mt < 4; mt++)
        #pragma unroll
        for (int nt = 0; nt < 8; nt++)
            #pragma unroll
            for (int q = 0; q < 4; q++) cfr[mt][nt][q] = 0.0f;

    const int nk = K >> 5;

    auto load_stage = [&](int ch, int s) {
        const int kc = ch * 32;
        const uint32_t sA = sbase + s * STAGE_BYTES + swz0;
        const uint32_t sB = sA + 16384;
        const float* ap = ag0 + kc;
        const float* bp = bg0 + kc;
        #pragma unroll
        for (int it = 0; it < 8; it++) {
            CP_ASYNC16(sA + it * 2048, ap + (size_t)it * 16 * K);
            CP_ASYNC16(sB + it * 2048, bp + (size_t)it * 16 * K);
        }
    };

    load_stage(0, 0);
    asm volatile("cp.async.commit_group;" ::: "memory");
    load_stage(1, 1);
    asm volatile("cp.async.commit_group;" ::: "memory");

    uint32_t af[2][16], bf[2][16];

    int s = 0;
    for (int ch = 0; ch < nk; ch++) {
        asm volatile("cp.async.wait_group 1;" ::: "memory");
        __syncthreads();
        const int s2 = (s + 2 >= NSTAGE) ? s - 1 : s + 2;
        if (ch + 2 < nk) load_stage(ch + 2, s2);
        asm volatile("cp.async.commit_group;" ::: "memory");

        const char* sA = smem + s * STAGE_BYTES;
        const char* sB = sA + 16384;

        auto load_frags = [&](int ks, int p) {
            const uint32_t kx = ks << 5;
            #pragma unroll
            for (int mt = 0; mt < 4; mt++) {
                const uint32_t ba = aOff[mt] ^ kx;
                af[p][mt*4+0] = lds32(sA, ba);
                af[p][mt*4+1] = lds32(sA, ba + 1024);
                af[p][mt*4+2] = lds32(sA, ba ^ 16);
                af[p][mt*4+3] = lds32(sA, (ba ^ 16) + 1024);
            }
            #pragma unroll
            for (int nt = 0; nt < 8; nt++) {
                const uint32_t bb = bOff[nt] ^ kx;
                bf[p][nt*2+0] = lds32(sB, bb);
                bf[p][nt*2+1] = lds32(sB, bb ^ 16);
            }
        };

        load_frags(0, 0);
        #pragma unroll
        for (int ks = 0; ks < 4; ks++) {
            const int p = ks & 1;
            if (ks < 3) load_frags(ks + 1, p ^ 1);
            #pragma unroll
            for (int mt = 0; mt < 4; mt++)
                #pragma unroll
                for (int nt = 0; nt < 8; nt++)
                    MMA_TF32(cfr[mt][nt], &af[p][mt*4], &bf[p][nt*2]);
        }
        s = (s + 1 >= NSTAGE) ? 0 : s + 1;
    }

    // Epilogue: thread owns rows (m0+mt*16+g, +8), cols n0+nt*8+t4*2 (+1)
    #pragma unroll
    for (int mt = 0; mt < 4; mt++) {
        #pragma unroll
        for (int half = 0; half < 2; half++) {
            const int ml = m0 + mt * 16 + g + half * 8;
            const size_t gm = (size_t)crow * 128 + ml;
            const float* rp = rowBias
                ? rowBias + (gm / rowsPerBatch) * (size_t)N + (size_t)ccol * 128
                : nullptr;
            float* Crow = C + gm * N + (size_t)ccol * 128;
            #pragma unroll
            for (int nt = 0; nt < 8; nt++) {
                const int cl = n0 + nt * 8 + t4 * 2;
                float v0 = cfr[mt][nt][half * 2 + 0];
                float v1 = cfr[mt][nt][half * 2 + 1];
                if (bias) { v0 += bias[(size_t)ccol * 128 + cl];
                            v1 += bias[(size_t)ccol * 128 + cl + 1]; }
                if (rp)   { v0 += rp[cl]; v1 += rp[cl + 1]; }
                if (cvtOut) { v0 = to_tf32(v0); v1 = to_tf32(v1); }
                *(float2*)(Crow + cl) = make_float2(v0, v1);
            }
        }
    }
}

// ---------------------------------------------------------------------------
// Tiled softmax over L + z.  One CTA per (b, 128-d tile); e tile staged in
// smem; single exp per element.  In-place: e and alpha are the same buffer.
// ---------------------------------------------------------------------------
#define SMX_SMEM (L_ * 128 * 4)     // 100352 bytes

__global__ __launch_bounds__(256, 2)
void softmax_z_kernel(float* __restrict__ e_alpha,
                      const float* __restrict__ fv,
                      float* __restrict__ z)
{
    extern __shared__ float es[];           // [196][128]
    __shared__ float red[2][128];

    const int b  = blockIdx.y;
    const int d0 = blockIdx.x * 128;
    const int tid = threadIdx.x;

    float* Eb = e_alpha + (size_t)b * L_ * D_ + d0;
    const float* Fb = fv + (size_t)b * L_ * D_ + d0;

    // load tile, coalesced
    #pragma unroll 7
    for (int i = tid; i < L_ * 128; i += 256) {
        const int r = i >> 7, c = i & 127;
        es[i] = Eb[(size_t)r * D_ + c];
    }
    __syncthreads();

    const int col = tid & 127, half = tid >> 7;
    const int r0 = half * 98;

    // pass A: max over this half's 98 rows
    float m = -INFINITY;
    #pragma unroll 7
    for (int r = 0; r < 98; r++)
        m = fmaxf(m, es[(r0 + r) * 128 + col]);
    red[half][col] = m;
    __syncthreads();
    m = fmaxf(red[0][col], red[1][col]);
    __syncthreads();                        // red reuse guard

    // pass B: exp + sum, overwrite smem with un-normalized a
    float sum = 0.0f;
    #pragma unroll 7
    for (int r = 0; r < 98; r++) {
        const int idx = (r0 + r) * 128 + col;
        const float a = __expf(es[idx] - m);
        es[idx] = a;
        sum += a;
    }
    red[half][col] = sum;
    __syncthreads();
    const float inv = 1.0f / (red[0][col] + red[1][col]);
    __syncthreads();                        // red reuse guard

    // pass C: normalized write-out + z accumulation
    float zz = 0.0f;
    #pragma unroll 7
    for (int r = 0; r < 98; r++) {
        const int rr = r0 + r;
        const float a = es[rr * 128 + col] * inv;
        Eb[(size_t)rr * D_ + col] = a;
        zz = fmaf(a, Fb[(size_t)rr * D_ + col], zz);
    }
    red[half][col] = zz;
    __syncthreads();
    if (half == 0)
        z[(size_t)b * D_ + d0 + col] = red[0][col] + red[1][col];
}

// ---------------------------------------------------------------------------
// kernel_launch
// ---------------------------------------------------------------------------
extern "C" void kernel_launch(void* const* d_in, const int* in_sizes, int n_in,
                              void* d_out, int out_size)
{
    const float* fv     = (const float*)d_in[0];
    const float* hidden = (const float*)d_in[1];
    const float* W_f    = (const float*)d_in[2];
    const float* b_f    = (const float*)d_in[3];
    const float* W_h    = (const float*)d_in[4];
    const float* b_h    = (const float*)d_in[5];
    const float* W_a    = (const float*)d_in[6];
    const float* b_a    = (const float*)d_in[7];

    float* z     = (float*)d_out;
    float* alpha = z + (size_t)B_ * D_;

    float *hsPtr, *tPtr, *WftPtr, *WatPtr;
    cudaGetSymbolAddress((void**)&hsPtr,  g_hs);
    cudaGetSymbolAddress((void**)&tPtr,   g_t);
    cudaGetSymbolAddress((void**)&WftPtr, g_Wft);
    cudaGetSymbolAddress((void**)&WatPtr, g_Wat);

    cudaFuncSetAttribute(gemm_tc, cudaFuncAttributeMaxDynamicSharedMemorySize,
                         SMEM_BYTES);
    cudaFuncSetAttribute(softmax_z_kernel,
                         cudaFuncAttributeMaxDynamicSharedMemorySize, SMX_SMEM);

    // 0) transpose weights to K-major + tf32 round
    transpose_k<<<dim3(I_ / 32, D_ / 32), dim3(32, 8)>>>(W_f, WftPtr, D_, I_);
    transpose_k<<<dim3(D_ / 32, I_ / 32), dim3(32, 8)>>>(W_a, WatPtr, I_, D_);

    // 1) hs = hidden @ W_h + b_h + b_f
    hs_kernel<<<dim3(B_, I_ / 128), 128>>>(hidden, W_h, b_h, b_f, hsPtr);

    // 2) t = fv @ W_f + hs[b]   M=12544, N=512, K=2048  (tf32-rounded out)
    gemm_tc<<<dim3(I_ / 128, M_ / 128), 128, SMEM_BYTES>>>(
        M_, I_, D_, fv, WftPtr, tPtr, nullptr, hsPtr, L_, 1);

    // 3) e = t @ W_a + b_a      M=12544, N=2048, K=512  (into alpha region)
    gemm_tc<<<dim3(D_ / 128, M_ / 128), 128, SMEM_BYTES>>>(
        M_, D_, I_, tPtr, WatPtr, alpha, b_a, nullptr, 1, 0);

    // 4) tiled softmax over L + z
    softmax_z_kernel<<<dim3(D_ / 128, B_), 256, SMX_SMEM>>>(alpha, fv, z);
}

// round 9
// speedup vs baseline: 1.4083x; 1.4083x over previous
#include <cuda_runtime.h>
#include <cuda_bf16.h>
#include <cstdint>
#include <math.h>

// Problem dims
#define B_  64
#define L_  196
#define D_  2048
#define I_  512
#define M_  (B_ * L_)   // 12544

// Scratch (allocation-free: __device__ globals)
__device__ float g_hs [B_ * I_];          // hs_shaped + b_h + b_f   [B, I]
__device__ float g_t  [(size_t)M_ * I_];  // fv@W_f + bias (tf32)    [B*L, I]
__device__ float g_Wft[(size_t)I_ * D_];  // W_f^T (tf32)            [I, D]
__device__ float g_Wat[(size_t)D_ * I_];  // W_a^T (tf32)            [D, I]

// ---------------------------------------------------------------------------
// helpers
// ---------------------------------------------------------------------------
__device__ __forceinline__ uint32_t smem_u32(const void* p) {
    uint32_t a;
    asm("{ .reg .u64 t; cvta.to.shared.u64 t, %1; cvt.u32.u64 %0, t; }"
        : "=r"(a) : "l"(p));
    return a;
}

// round-to-nearest to tf32 (keep top 19 bits)
__device__ __forceinline__ float to_tf32(float v) {
    uint32_t u = __float_as_uint(v);
    u = (u + 0x1000u) & 0xFFFFE000u;
    return __uint_as_float(u);
}

#define MMA_TF32(c, a, b) \
    asm volatile("mma.sync.aligned.m16n8k8.row.col.f32.tf32.tf32.f32 " \
        "{%0,%1,%2,%3}, {%4,%5,%6,%7}, {%8,%9}, {%0,%1,%2,%3};" \
        : "+f"((c)[0]), "+f"((c)[1]), "+f"((c)[2]), "+f"((c)[3]) \
        : "r"((a)[0]), "r"((a)[1]), "r"((a)[2]), "r"((a)[3]), \
          "r"((b)[0]), "r"((b)[1]))

#define CP_ASYNC16(saddr, gptr) \
    asm volatile("cp.async.cg.shared.global [%0], [%1], 16;" \
                 :: "r"(saddr), "l"(gptr) : "memory")

// 4-matrix ldmatrix (b16 view of 8x4 f32 submatrices)
#define LDSM4(r, addr) \
    asm volatile("ldmatrix.sync.aligned.m8n8.x4.shared.b16 {%0,%1,%2,%3}, [%4];" \
        : "=r"((r)[0]), "=r"((r)[1]), "=r"((r)[2]), "=r"((r)[3]) : "r"(addr))

// ---------------------------------------------------------------------------
// Kernel A: g_hs[b,i] = b_f[i] + b_h[i] + sum_k hidden[b,k] * W_h[k,i]
// ---------------------------------------------------------------------------
__global__ __launch_bounds__(128)
void hs_kernel(const float* __restrict__ hidden,
               const float* __restrict__ W_h,
               const float* __restrict__ b_h,
               const float* __restrict__ b_f,
               float* __restrict__ out)
{
    __shared__ float h[I_];
    const int b = blockIdx.x;
    for (int k = threadIdx.x; k < I_; k += 128)
        h[k] = hidden[b * I_ + k];
    __syncthreads();

    const int i = blockIdx.y * 128 + threadIdx.x;
    float acc = b_h[i] + b_f[i];
    #pragma unroll 8
    for (int k = 0; k < I_; k++)
        acc = fmaf(h[k], W_h[(size_t)k * I_ + i], acc);
    out[b * I_ + i] = acc;
}

// ---------------------------------------------------------------------------
// Transpose + tf32 round: in[R][C] -> out[C][R]
// ---------------------------------------------------------------------------
__global__ __launch_bounds__(256)
void transpose_k(const float* __restrict__ in, float* __restrict__ out,
                 int R, int Cc)
{
    __shared__ float t[32][33];
    const int bx = blockIdx.x * 32;
    const int by = blockIdx.y * 32;
    const int x = threadIdx.x, y = threadIdx.y;
    #pragma unroll
    for (int i = 0; i < 32; i += 8)
        t[y + i][x] = in[(size_t)(by + y + i) * Cc + bx + x];
    __syncthreads();
    #pragma unroll
    for (int i = 0; i < 32; i += 8)
        out[(size_t)(bx + y + i) * R + by + x] = to_tf32(t[x][y + i]);
}

// ---------------------------------------------------------------------------
// tf32 mma.sync GEMM: C[M,N] = A[M,K] @ Bt[N,K]^T (+bias[N]) (+rowBias)
// CTA 128x128x32, 3 stages (96KB), 256 threads (8 warps, 64x32 tiles),
// 2 CTAs/SM. Fragment loads via ldmatrix.x4 (6 LDSM per k-step).
// ---------------------------------------------------------------------------
#define NSTAGE 3
#define STAGE_BYTES 32768           // A 16KB + B 16KB
#define SMEM_BYTES (NSTAGE * STAGE_BYTES)

__global__ __launch_bounds__(256, 2)
void gemm_tc(int M, int N, int K,
             const float* __restrict__ A,
             const float* __restrict__ Bt,
             float* __restrict__ C,
             const float* __restrict__ bias,
             const float* __restrict__ rowBias,
             int rowsPerBatch, int cvtOut)
{
    extern __shared__ __align__(128) char smem[];
    const uint32_t sbase = smem_u32(smem);
    const int tid = threadIdx.x;
    const int wid = tid >> 5;
    const int lid = tid & 31;
    const int g   = lid >> 2;      // 0..7
    const int t4  = lid & 3;       // 0..3

    const int m0 = (wid >> 2) * 64;
    const int n0 = (wid & 3) * 32;

    const int crow = blockIdx.y, ccol = blockIdx.x;
    const float* Ab = A  + (size_t)crow * 128 * K;
    const float* Bb = Bt + (size_t)ccol * 128 * K;

    // ldmatrix lane-address bases (within a stage); addr(ks) = base ^ (ks<<5)
    // A LDSM (per mt): matrices {rows 0-7,k0-3},{rows 8-15,k0-3},{0-7,k4-7},{8-15,k4-7}
    uint32_t aOff[4], bOff[2];
    {
        const int arow_l = lid & 15;           // row within 16-row tile
        const uint32_t ahi = (uint32_t)(lid >> 4) << 4;
        #pragma unroll
        for (int mt = 0; mt < 4; mt++) {
            const int row = m0 + mt * 16 + arow_l;
            aOff[mt] = row * 128 + (ahi ^ ((row & 7) << 4));
        }
        // B LDSM j covers nt pair (2j, 2j+1):
        // matrices {n rows 0-7,k0-3},{0-7,k4-7},{8-15,k0-3},{8-15,k4-7}
        const int brow_l = (lid & 7) + ((lid >> 4) << 3);
        const uint32_t bhi = (uint32_t)((lid >> 3) & 1) << 4;
        #pragma unroll
        for (int j = 0; j < 2; j++) {
            const int row = n0 + j * 16 + brow_l;
            bOff[j] = row * 128 + (bhi ^ ((row & 7) << 4));
        }
    }

    // Precomputed gmem->smem copy slots
    uint32_t swz[4];
    const float *ag[4], *bg[4];
    #pragma unroll
    for (int it = 0; it < 4; it++) {
        const int j = tid + it * 256;
        const int row = j >> 3, c4 = j & 7;
        swz[it] = row * 128 + ((c4 << 4) ^ ((row & 7) << 4));
        ag[it] = Ab + (size_t)row * K + c4 * 4;
        bg[it] = Bb + (size_t)row * K + c4 * 4;
    }

    float cfr[4][4][4];
    #pragma unroll
    for (int mt = 0; mt < 4; mt++)
        #pragma unroll
        for (int nt = 0; nt < 4; nt++)
            #pragma unroll
            for (int q = 0; q < 4; q++) cfr[mt][nt][q] = 0.0f;

    const int nk = K >> 5;

    auto load_stage = [&](int ch, int s) {
        const int kc = ch * 32;
        const uint32_t sA = sbase + s * STAGE_BYTES;
        const uint32_t sB = sA + 16384;
        #pragma unroll
        for (int it = 0; it < 4; it++) {
            CP_ASYNC16(sA + swz[it], ag[it] + kc);
            CP_ASYNC16(sB + swz[it], bg[it] + kc);
        }
    };

    load_stage(0, 0);
    asm volatile("cp.async.commit_group;" ::: "memory");
    load_stage(1, 1);
    asm volatile("cp.async.commit_group;" ::: "memory");

    uint32_t af[2][16], bf[2][8];

    int s = 0;
    for (int ch = 0; ch < nk; ch++) {
        asm volatile("cp.async.wait_group 1;" ::: "memory");
        __syncthreads();
        const int s2 = (s + 2 >= NSTAGE) ? s - 1 : s + 2;
        if (ch + 2 < nk) load_stage(ch + 2, s2);
        asm volatile("cp.async.commit_group;" ::: "memory");

        const uint32_t sAa = sbase + s * STAGE_BYTES;
        const uint32_t sBa = sAa + 16384;

        auto load_frags = [&](int ks, int p) {
            const uint32_t kx = ks << 5;
            #pragma unroll
            for (int mt = 0; mt < 4; mt++)
                LDSM4(&af[p][mt * 4], sAa + (aOff[mt] ^ kx));
            #pragma unroll
            for (int j = 0; j < 2; j++)
                LDSM4(&bf[p][j * 4], sBa + (bOff[j] ^ kx));
        };

        load_frags(0, 0);
        #pragma unroll
        for (int ks = 0; ks < 4; ks++) {
            const int p = ks & 1;
            if (ks < 3) load_frags(ks + 1, p ^ 1);
            #pragma unroll
            for (int mt = 0; mt < 4; mt++)
                #pragma unroll
                for (int nt = 0; nt < 4; nt++)
                    MMA_TF32(cfr[mt][nt], &af[p][mt*4], &bf[p][nt*2]);
        }
        s = (s + 1 >= NSTAGE) ? 0 : s + 1;
    }

    // Epilogue: thread owns rows (m0+mt*16+g, +8), cols n0+nt*8+t4*2 (+1)
    #pragma unroll
    for (int mt = 0; mt < 4; mt++) {
        #pragma unroll
        for (int half = 0; half < 2; half++) {
            const int ml = m0 + mt * 16 + g + half * 8;
            const size_t gm = (size_t)crow * 128 + ml;
            const float* rp = rowBias
                ? rowBias + (gm / rowsPerBatch) * (size_t)N + (size_t)ccol * 128
                : nullptr;
            float* Crow = C + gm * N + (size_t)ccol * 128;
            #pragma unroll
            for (int nt = 0; nt < 4; nt++) {
                const int cl = n0 + nt * 8 + t4 * 2;
                float v0 = cfr[mt][nt][half * 2 + 0];
                float v1 = cfr[mt][nt][half * 2 + 1];
                if (bias) { v0 += bias[(size_t)ccol * 128 + cl];
                            v1 += bias[(size_t)ccol * 128 + cl + 1]; }
                if (rp)   { v0 += rp[cl]; v1 += rp[cl + 1]; }
                if (cvtOut) { v0 = to_tf32(v0); v1 = to_tf32(v1); }
                *(float2*)(Crow + cl) = make_float2(v0, v1);
            }
        }
    }
}

// ---------------------------------------------------------------------------
// Tiled softmax over L + z.  One CTA per (b, 128-d tile); e tile staged in
// smem; single exp per element.  In-place: e and alpha are the same buffer.
// ---------------------------------------------------------------------------
#define SMX_SMEM (L_ * 128 * 4)     // 100352 bytes

__global__ __launch_bounds__(256, 2)
void softmax_z_kernel(float* __restrict__ e_alpha,
                      const float* __restrict__ fv,
                      float* __restrict__ z)
{
    extern __shared__ float es[];           // [196][128]
    __shared__ float red[2][128];

    const int b  = blockIdx.y;
    const int d0 = blockIdx.x * 128;
    const int tid = threadIdx.x;

    float* Eb = e_alpha + (size_t)b * L_ * D_ + d0;
    const float* Fb = fv + (size_t)b * L_ * D_ + d0;

    // load tile, coalesced
    #pragma unroll 7
    for (int i = tid; i < L_ * 128; i += 256) {
        const int r = i >> 7, c = i & 127;
        es[i] = Eb[(size_t)r * D_ + c];
    }
    __syncthreads();

    const int col = tid & 127, half = tid >> 7;
    const int r0 = half * 98;

    // pass A: max over this half's 98 rows
    float m = -INFINITY;
    #pragma unroll 7
    for (int r = 0; r < 98; r++)
        m = fmaxf(m, es[(r0 + r) * 128 + col]);
    red[half][col] = m;
    __syncthreads();
    m = fmaxf(red[0][col], red[1][col]);
    __syncthreads();                        // red reuse guard

    // pass B: exp + sum, overwrite smem with un-normalized a
    float sum = 0.0f;
    #pragma unroll 7
    for (int r = 0; r < 98; r++) {
        const int idx = (r0 + r) * 128 + col;
        const float a = __expf(es[idx] - m);
        es[idx] = a;
        sum += a;
    }
    red[half][col] = sum;
    __syncthreads();
    const float inv = 1.0f / (red[0][col] + red[1][col]);
    __syncthreads();                        // red reuse guard

    // pass C: normalized write-out + z accumulation
    float zz = 0.0f;
    #pragma unroll 7
    for (int r = 0; r < 98; r++) {
        const int rr = r0 + r;
        const float a = es[rr * 128 + col] * inv;
        Eb[(size_t)rr * D_ + col] = a;
        zz = fmaf(a, Fb[(size_t)rr * D_ + col], zz);
    }
    red[half][col] = zz;
    __syncthreads();
    if (half == 0)
        z[(size_t)b * D_ + d0 + col] = red[0][col] + red[1][col];
}

// ---------------------------------------------------------------------------
// kernel_launch
// ---------------------------------------------------------------------------
extern "C" void kernel_launch(void* const* d_in, const int* in_sizes, int n_in,
                              void* d_out, int out_size)
{
    const float* fv     = (const float*)d_in[0];
    const float* hidden = (const float*)d_in[1];
    const float* W_f    = (const float*)d_in[2];
    const float* b_f    = (const float*)d_in[3];
    const float* W_h    = (const float*)d_in[4];
    const float* b_h    = (const float*)d_in[5];
    const float* W_a    = (const float*)d_in[6];
    const float* b_a    = (const float*)d_in[7];

    float* z     = (float*)d_out;
    float* alpha = z + (size_t)B_ * D_;

    float *hsPtr, *tPtr, *WftPtr, *WatPtr;
    cudaGetSymbolAddress((void**)&hsPtr,  g_hs);
    cudaGetSymbolAddress((void**)&tPtr,   g_t);
    cudaGetSymbolAddress((void**)&WftPtr, g_Wft);
    cudaGetSymbolAddress((void**)&WatPtr, g_Wat);

    cudaFuncSetAttribute(gemm_tc, cudaFuncAttributeMaxDynamicSharedMemorySize,
                         SMEM_BYTES);
    cudaFuncSetAttribute(softmax_z_kernel,
                         cudaFuncAttributeMaxDynamicSharedMemorySize, SMX_SMEM);

    // 0) transpose weights to K-major + tf32 round
    transpose_k<<<dim3(I_ / 32, D_ / 32), dim3(32, 8)>>>(W_f, WftPtr, D_, I_);
    transpose_k<<<dim3(D_ / 32, I_ / 32), dim3(32, 8)>>>(W_a, WatPtr, I_, D_);

    // 1) hs = hidden @ W_h + b_h + b_f
    hs_kernel<<<dim3(B_, I_ / 128), 128>>>(hidden, W_h, b_h, b_f, hsPtr);

    // 2) t = fv @ W_f + hs[b]   M=12544, N=512, K=2048  (tf32-rounded out)
    gemm_tc<<<dim3(I_ / 128, M_ / 128), 256, SMEM_BYTES>>>(
        M_, I_, D_, fv, WftPtr, tPtr, nullptr, hsPtr, L_, 1);

    // 3) e = t @ W_a + b_a      M=12544, N=2048, K=512  (into alpha region)
    gemm_tc<<<dim3(D_ / 128, M_ / 128), 256, SMEM_BYTES>>>(
        M_, D_, I_, tPtr, WatPtr, alpha, b_a, nullptr, 1, 0);

    // 4) tiled softmax over L + z
    softmax_z_kernel<<<dim3(D_ / 128, B_), 256, SMX_SMEM>>>(alpha, fv, z);
}